// round 1
// baseline (speedup 1.0000x reference)
#include <cuda_runtime.h>
#include <math.h>

// Problem constants
#define Bz 2
#define Sz 4096
#define Dz 1024
#define Fz 4096
#define Mz (Bz * Sz)   // 8192

// ---------------------------------------------------------------------------
// Scratch (allocation-free: __device__ globals)
// ---------------------------------------------------------------------------
__device__ float g_Q [(size_t)Mz * Dz];       // 33.5 MB
__device__ float g_K [(size_t)Mz * Dz];
__device__ float g_V [(size_t)Mz * Dz];
__device__ float g_A [(size_t)Mz * 2 * Dz];   // 67 MB (a_real | a_imag)
__device__ float g_G [(size_t)Mz * Dz];
__device__ float g_Y [(size_t)Mz * Dz];       // real(y) after gating
__device__ float g_Yo[(size_t)Mz * Dz];       // y @ Wo
__device__ float g_U [(size_t)Mz * Dz];       // LN1 output (residual stream)
__device__ float g_H [(size_t)Mz * Fz];       // 134 MB FFN hidden
__device__ float g_O2[(size_t)Mz * Dz];       // FFN output

// ---------------------------------------------------------------------------
// FP32 tiled GEMM: C[M,N] = A[M,K] @ B[K,N] (+bias) (+gelu)
// 128x128 block tile, 16 K-tile, 8x8 per thread, 256 threads.
// act: 0 = none, 1 = +bias, 2 = +bias then tanh-gelu
// ---------------------------------------------------------------------------
__global__ __launch_bounds__(256) void sgemm_k(
    const float* __restrict__ A, const float* __restrict__ Bm,
    const float* __restrict__ bias, float* __restrict__ C,
    int M, int N, int K, int act)
{
    __shared__ float As[16][128];
    __shared__ float Bs[16][128];

    const int bm  = blockIdx.y * 128;
    const int bn  = blockIdx.x * 128;
    const int tid = threadIdx.x;
    const int tx  = tid & 15;   // 0..15 -> N direction
    const int ty  = tid >> 4;   // 0..15 -> M direction

    float acc[8][8];
#pragma unroll
    for (int i = 0; i < 8; i++)
#pragma unroll
        for (int j = 0; j < 8; j++) acc[i][j] = 0.0f;

    const int aRow0 = tid >> 2;        // 0..63
    const int aCol4 = (tid & 3) * 4;   // 0,4,8,12
    const int bRow0 = tid >> 5;        // 0..7
    const int bCol4 = (tid & 31) * 4;  // 0..124

    for (int k0 = 0; k0 < K; k0 += 16) {
        // A tile (128 x 16), stored transposed As[k][m]
#pragma unroll
        for (int p = 0; p < 2; p++) {
            int row = aRow0 + p * 64;
            float4 va = *reinterpret_cast<const float4*>(
                &A[(size_t)(bm + row) * K + k0 + aCol4]);
            As[aCol4 + 0][row] = va.x;
            As[aCol4 + 1][row] = va.y;
            As[aCol4 + 2][row] = va.z;
            As[aCol4 + 3][row] = va.w;
        }
        // B tile (16 x 128)
#pragma unroll
        for (int p = 0; p < 2; p++) {
            int row = bRow0 + p * 8;
            float4 vb = *reinterpret_cast<const float4*>(
                &Bm[(size_t)(k0 + row) * N + bn + bCol4]);
            *reinterpret_cast<float4*>(&Bs[row][bCol4]) = vb;
        }
        __syncthreads();

#pragma unroll
        for (int k = 0; k < 16; k++) {
            float ra[8], rb[8];
            *reinterpret_cast<float4*>(ra)     = *reinterpret_cast<const float4*>(&As[k][ty * 8]);
            *reinterpret_cast<float4*>(ra + 4) = *reinterpret_cast<const float4*>(&As[k][ty * 8 + 4]);
            *reinterpret_cast<float4*>(rb)     = *reinterpret_cast<const float4*>(&Bs[k][tx * 8]);
            *reinterpret_cast<float4*>(rb + 4) = *reinterpret_cast<const float4*>(&Bs[k][tx * 8 + 4]);
#pragma unroll
            for (int i = 0; i < 8; i++)
#pragma unroll
                for (int j = 0; j < 8; j++)
                    acc[i][j] = fmaf(ra[i], rb[j], acc[i][j]);
        }
        __syncthreads();
    }

    // Epilogue
#pragma unroll
    for (int i = 0; i < 8; i++) {
        int row = bm + ty * 8 + i;
#pragma unroll
        for (int j = 0; j < 8; j++) {
            int col = bn + tx * 8 + j;
            float v = acc[i][j];
            if (act >= 1) v += bias[col];
            if (act == 2) {
                // JAX default gelu (approximate=True, tanh form)
                float x3 = v * v * v;
                v = 0.5f * v * (1.0f + tanhf(0.7978845608028654f * (v + 0.044715f * x3)));
            }
            C[(size_t)row * N + col] = v;
        }
    }
}

// ---------------------------------------------------------------------------
// GateLoop scan: per (b,d) channel, sequential over t.
//   a_c   = sigmoid(|a|) * a/|a|                (complex, |a_c|<1)
//   h_t   = a_c * h_{t-1} + k_t*v_t             (complex, kv real)
//   y_t   = q_t * Re(h_t) * silu(g_t)           (only real part survives @Wo)
// ---------------------------------------------------------------------------
__global__ void gateloop_kernel(
    const float* __restrict__ q, const float* __restrict__ k,
    const float* __restrict__ v, const float* __restrict__ a,
    const float* __restrict__ g, float* __restrict__ y)
{
    int c = blockIdx.x * blockDim.x + threadIdx.x;  // 0..B*D-1
    if (c >= Bz * Dz) return;
    int b = c >> 10;          // / Dz
    int d = c & (Dz - 1);     // % Dz
    size_t base  = (size_t)b * Sz * Dz + d;
    size_t abase = (size_t)b * Sz * 2 * Dz + d;

    float hr = 0.0f, hi = 0.0f;
    for (int t = 0; t < Sz; t++) {
        size_t i  = base  + (size_t)t * Dz;
        size_t ia = abase + (size_t)t * 2 * Dz;
        float ar = a[ia];
        float ai = a[ia + Dz];
        float mag = sqrtf(fmaf(ar, ar, ai * ai));
        float s   = 1.0f / (1.0f + __expf(-mag));   // sigmoid(|a|)
        float inv = s / fmaxf(mag, 1e-30f);
        float arr = ar * inv;
        float aii = ai * inv;
        float kv  = k[i] * v[i];
        float nhr = fmaf(arr, hr, fmaf(-aii, hi, kv));
        float nhi = fmaf(arr, hi, aii * hr);
        hr = nhr; hi = nhi;
        float gg  = g[i];
        float sil = gg / (1.0f + __expf(-gg));      // silu(g), g is real
        y[i] = q[i] * hr * sil;
    }
}

// ---------------------------------------------------------------------------
// out = LayerNorm(x + res) * scale + bias ; one block per row, 256 threads
// ---------------------------------------------------------------------------
__global__ __launch_bounds__(256) void add_ln_kernel(
    const float* __restrict__ x, const float* __restrict__ res,
    const float* __restrict__ scale, const float* __restrict__ bias,
    float* __restrict__ out)
{
    __shared__ float red[8];
    int row = blockIdx.x;
    int tid = threadIdx.x;
    const float* xr = x   + (size_t)row * Dz;
    const float* rr = res + (size_t)row * Dz;

    float vals[4];
    float sum = 0.0f;
#pragma unroll
    for (int j = 0; j < 4; j++) {
        int col = tid + j * 256;
        vals[j] = xr[col] + rr[col];
        sum += vals[j];
    }
#pragma unroll
    for (int o = 16; o > 0; o >>= 1) sum += __shfl_xor_sync(0xffffffffu, sum, o);
    if ((tid & 31) == 0) red[tid >> 5] = sum;
    __syncthreads();
    float tot = 0.0f;
#pragma unroll
    for (int w = 0; w < 8; w++) tot += red[w];
    float mean = tot * (1.0f / (float)Dz);

    float vs = 0.0f;
#pragma unroll
    for (int j = 0; j < 4; j++) {
        float dlt = vals[j] - mean;
        vs += dlt * dlt;
    }
#pragma unroll
    for (int o = 16; o > 0; o >>= 1) vs += __shfl_xor_sync(0xffffffffu, vs, o);
    __syncthreads();   // protect red[] reuse
    if ((tid & 31) == 0) red[tid >> 5] = vs;
    __syncthreads();
    float vtot = 0.0f;
#pragma unroll
    for (int w = 0; w < 8; w++) vtot += red[w];
    float var  = vtot * (1.0f / (float)Dz);
    float rstd = rsqrtf(var + 1e-6f);

#pragma unroll
    for (int j = 0; j < 4; j++) {
        int col = tid + j * 256;
        out[(size_t)row * Dz + col] =
            (vals[j] - mean) * rstd * scale[col] + bias[col];
    }
}

// ---------------------------------------------------------------------------
// Launch
// ---------------------------------------------------------------------------
extern "C" void kernel_launch(void* const* d_in, const int* in_sizes, int n_in,
                              void* d_out, int out_size)
{
    const float* x    = (const float*)d_in[0];
    const float* Wq   = (const float*)d_in[1];
    const float* Wk   = (const float*)d_in[2];
    const float* Wv   = (const float*)d_in[3];
    const float* Wa   = (const float*)d_in[4];
    const float* Wg   = (const float*)d_in[5];
    const float* Wo   = (const float*)d_in[6];
    const float* ln1s = (const float*)d_in[7];
    const float* ln1b = (const float*)d_in[8];
    const float* W1   = (const float*)d_in[9];
    const float* b1   = (const float*)d_in[10];
    const float* W2   = (const float*)d_in[11];
    const float* b2   = (const float*)d_in[12];
    const float* ln2s = (const float*)d_in[13];
    const float* ln2b = (const float*)d_in[14];
    float* out = (float*)d_out;

    float *Q, *K, *V, *A, *G, *Y, *Yo, *U, *H, *O2;
    cudaGetSymbolAddress((void**)&Q,  g_Q);
    cudaGetSymbolAddress((void**)&K,  g_K);
    cudaGetSymbolAddress((void**)&V,  g_V);
    cudaGetSymbolAddress((void**)&A,  g_A);
    cudaGetSymbolAddress((void**)&G,  g_G);
    cudaGetSymbolAddress((void**)&Y,  g_Y);
    cudaGetSymbolAddress((void**)&Yo, g_Yo);
    cudaGetSymbolAddress((void**)&U,  g_U);
    cudaGetSymbolAddress((void**)&H,  g_H);
    cudaGetSymbolAddress((void**)&O2, g_O2);

    dim3 blk(256);
    dim3 gD (Dz / 128,     Mz / 128);   // N=1024
    dim3 g2D(2 * Dz / 128, Mz / 128);   // N=2048
    dim3 gF (Fz / 128,     Mz / 128);   // N=4096

    // Projections
    sgemm_k<<<gD,  blk>>>(x, Wq, nullptr, Q, Mz, Dz,     Dz, 0);
    sgemm_k<<<gD,  blk>>>(x, Wk, nullptr, K, Mz, Dz,     Dz, 0);
    sgemm_k<<<gD,  blk>>>(x, Wv, nullptr, V, Mz, Dz,     Dz, 0);
    sgemm_k<<<g2D, blk>>>(x, Wa, nullptr, A, Mz, 2 * Dz, Dz, 0);
    sgemm_k<<<gD,  blk>>>(x, Wg, nullptr, G, Mz, Dz,     Dz, 0);

    // Gated complex scan (real output)
    gateloop_kernel<<<(Bz * Dz) / 256, 256>>>(Q, K, V, A, G, Y);

    // Output projection + residual + LN1
    sgemm_k<<<gD, blk>>>(Y, Wo, nullptr, Yo, Mz, Dz, Dz, 0);
    add_ln_kernel<<<Mz, 256>>>(Yo, x, ln1s, ln1b, U);

    // FFN
    sgemm_k<<<gF, blk>>>(U, W1, b1, H,  Mz, Fz, Dz, 2);  // +bias, gelu
    sgemm_k<<<gD, blk>>>(H, W2, b2, O2, Mz, Dz, Fz, 1);  // +bias

    // Residual + LN2 -> out
    add_ln_kernel<<<Mz, 256>>>(O2, U, ln2s, ln2b, out);
}